// round 13
// baseline (speedup 1.0000x reference)
#include <cuda_runtime.h>
#include <cuda_fp16.h>
#include <cstdint>

// ---------------------------------------------------------------------------
// Problem constants
// ---------------------------------------------------------------------------
#define Nn 5570          // nodes
#define NT 384           // aggregation columns = B(16) * D(4) * 6
#define MP 5632          // M padded: 44 tiles of 128
#define KK 5632          // K padded
#define KHALF 2816       // K per z-slice
#define MT 44            // row tiles
#define CT 3             // col tiles (3 x 128 = 384)
#define NIT3 (KHALF / 64) // GEMM k-iterations per slice (44)

// ---------------------------------------------------------------------------
// Device scratch
// ---------------------------------------------------------------------------
__device__ __align__(128) uint32_t g_A[(size_t)MP * KK / 2];
__device__ __align__(128) uint32_t g_B[(size_t)KK * NT / 2];
__device__ float g_T0[(size_t)KK * NT];     // k=0 (identity) per-node partials
__device__ float g_rowinv[MP];
__device__ float g_Agg0[(size_t)MP * NT];   // K-half 0 partial (rowinv applied)
__device__ float g_Agg1[(size_t)MP * NT];   // K-half 1 partial (rowinv applied)
__device__ unsigned int g_gmax2_bits = 0u;  // max_m |e_m|^2 bits (atomicMax is
                                            // idempotent across graph replays)

// ---------------------------------------------------------------------------
// Helpers
// ---------------------------------------------------------------------------
__device__ __forceinline__ uint32_t smem_u32(const void* p) {
    uint32_t a;
    asm("{ .reg .u64 t; cvta.to.shared.u64 t, %1; cvt.u32.u64 %0, t; }" : "=r"(a) : "l"(p));
    return a;
}

// Fast exp on the FMA pipe for arg <= 0, arg >= -90. ~4e-5 relative error.
__device__ __forceinline__ float fexpn(float arg) {
    float t = arg * 1.4426950408889634f;
    float km = t + 12582912.0f;                 // round-to-nearest magic
    int   ki = __float_as_int(km);
    float f  = t - (km - 12582912.0f);          // f in [-0.5, 0.5]
    float p  = 9.6180691e-3f;
    p = fmaf(p, f, 5.5504109e-2f);
    p = fmaf(p, f, 2.4022651e-1f);
    p = fmaf(p, f, 6.9314718e-1f);
    p = fmaf(p, f, 1.0f);
    float sc = __int_as_float((ki - (0x4B400000 - 127)) << 23);  // 2^round(t)
    return p * sc;
}

// ---------------------------------------------------------------------------
// Micro-kernel: global max of |e_m|^2
// ---------------------------------------------------------------------------
__global__ void __launch_bounds__(256) normmax_kernel(const float* __restrict__ E) {
    int m = blockIdx.x * 256 + threadIdx.x;
    float v = 0.f;
    if (m < Nn) {
        float4 em = ((const float4*)E)[m];
        v = fmaf(em.x, em.x, fmaf(em.y, em.y, fmaf(em.z, em.z, em.w * em.w)));
    }
    #pragma unroll
    for (int o = 16; o > 0; o >>= 1) v = fmaxf(v, __shfl_xor_sync(0xffffffffu, v, o));
    if ((threadIdx.x & 31) == 0)
        atomicMax(&g_gmax2_bits, __float_as_uint(v));  // positive floats: uint order
}

// ---------------------------------------------------------------------------
// Kernel 1 (fused): blocks [0, 704): bounded-softmax P -> fp16 (single pass).
//                   blocks [704, 880): T^T (k=1 -> fp16 B) and T0 (k=0 -> fp32).
// ---------------------------------------------------------------------------
__global__ void __launch_bounds__(256) fused_prep_kernel(
    const float* __restrict__ E, const float* __restrict__ x,
    const float* __restrict__ wg, const float* __restrict__ wu)
{
    int tid = threadIdx.x;
    if (blockIdx.x < MP / 8) {
        // ---------------- exp part: one warp per row, single pass -------------
        int row  = blockIdx.x * 8 + (tid >> 5);
        int lane = tid & 31;
        const float4* E4 = (const float4*)E;
        bool valid = (row < Nn);
        float4 en = make_float4(0.f, 0.f, 0.f, 0.f);
        if (valid) en = E4[row];
        float en2 = fmaf(en.x, en.x, fmaf(en.y, en.y, fmaf(en.z, en.z, en.w * en.w)));
        float gmax2 = __uint_as_float(g_gmax2_bits);
        // Cauchy-Schwarz bound: M >= max_m en.em  (em includes en => M >= en2 >= 0)
        float M = sqrtf(en2 * gmax2);

        size_t rbase = (size_t)row * (KK / 2);
        float sum = 0.f;
        for (int kc = 0; kc < KK / 64; kc++) {
            int k0 = kc * 64 + lane * 2;
            float p0 = 0.f, p1 = 0.f;
            if (valid && k0 < Nn) {
                float4 e0 = __ldg(&E4[k0]);
                float4 e1 = __ldg(&E4[k0 + 1]);
                float z0 = fmaf(en.x, e0.x, fmaf(en.y, e0.y, fmaf(en.z, e0.z, en.w * e0.w)));
                float z1 = fmaf(en.x, e1.x, fmaf(en.y, e1.y, fmaf(en.z, e1.z, en.w * e1.w)));
                p0 = fexpn(fmaxf(z0, 0.f) - M);
                p1 = fexpn(fmaxf(z1, 0.f) - M);
            }
            sum += p0 + p1;
            __half2 h = __floats2half2_rn(p0, p1);
            g_A[rbase + kc * 32 + lane] = *reinterpret_cast<uint32_t*>(&h);
        }
        #pragma unroll
        for (int o = 16; o > 0; o >>= 1) sum += __shfl_xor_sync(0xffffffffu, sum, o);
        if (valid && lane == 0) g_rowinv[row] = 1.f / sum;
    } else {
        // -------- T parts: 16 m-pairs x 16 batches per block, k=1 and k=0 ------
        __shared__ float sW1[35][24];  // [i][d*6+o], k=1 support weights
        __shared__ float sW0[35][24];  // [i][d*6+o], k=0 (identity) weights
        for (int idx = tid; idx < 35 * 24; idx += 256) {
            int i = idx / 24, j = idx % 24, d = j / 6, o = j % 6;
            sW1[i][j] = (o < 4) ? wg[((d * 2 + 1) * 37 + i) * 4 + o]
                                : wu[((d * 2 + 1) * 37 + i) * 2 + (o - 4)];
            sW0[i][j] = (o < 4) ? wg[((d * 2) * 37 + i) * 4 + o]
                                : wu[((d * 2) * 37 + i) * 2 + (o - 4)];
        }
        __syncthreads();
        int bb = blockIdx.x - MP / 8;
        int mp = bb * 16 + (tid >> 4);   // m-pair index (0..2815)
        int b  = tid & 15;
        int m0 = mp * 2;
        float a1k[24], a1z[24], a2k[24], a2z[24];  // row0 k1/k0, row1 k1/k0
        #pragma unroll
        for (int j = 0; j < 24; j++) { a1k[j] = 0.f; a1z[j] = 0.f; a2k[j] = 0.f; a2z[j] = 0.f; }
        if (m0 < Nn) {
            const float* xp = x + ((size_t)b * Nn + m0) * 35;
            for (int i = 0; i < 35; i++) {
                float xv = xp[i];
                #pragma unroll
                for (int j = 0; j < 24; j++) {
                    a1k[j] = fmaf(xv, sW1[i][j], a1k[j]);
                    a1z[j] = fmaf(xv, sW0[i][j], a1z[j]);
                }
            }
        }
        if (m0 + 1 < Nn) {
            const float* xp = x + ((size_t)b * Nn + m0 + 1) * 35;
            for (int i = 0; i < 35; i++) {
                float xv = xp[i];
                #pragma unroll
                for (int j = 0; j < 24; j++) {
                    a2k[j] = fmaf(xv, sW1[i][j], a2k[j]);
                    a2z[j] = fmaf(xv, sW0[i][j], a2z[j]);
                }
            }
        }
        #pragma unroll
        for (int r = 0; r < 2; r++) {
            const float* ak = r ? a2k : a1k;
            const float* az = r ? a2z : a1z;
            size_t baseB = (size_t)(m0 + r) * (NT / 2) + b * 12;
            #pragma unroll
            for (int j = 0; j < 12; j++) {
                __half2 h = __floats2half2_rn(ak[2 * j], ak[2 * j + 1]);
                g_B[baseB + j] = *reinterpret_cast<uint32_t*>(&h);
            }
            float* t0p = g_T0 + (size_t)(m0 + r) * NT + b * 24;
            #pragma unroll
            for (int j = 0; j < 12; j++) {
                float2 v = make_float2(az[2 * j], az[2 * j + 1]);
                *(float2*)&t0p[2 * j] = v;
            }
        }
    }
}

// ---------------------------------------------------------------------------
// Kernel 2: GEMM partials Agg[z] = rowinv * (P[:, zK:zK+2816] @ T[zK:...]).
// Grid (44, 3, 2); CTA 128x128xKHALF, 4 warps (64x64 tiles), BK=64,
// 3-stage cp.async pipeline + register double-buffering at k16 granularity.
// 2 CTAs/SM (uncorrelated barriers). A pitch 144, B pitch 272 (conflict-free).
// ---------------------------------------------------------------------------
#define APITCH3 144
#define BPITCH3 272
#define ASZ3 (128 * APITCH3)          // 18432
#define BSZ3 (64 * BPITCH3)           // 17408
#define BOFF3 ASZ3
#define STAGE3 (ASZ3 + BSZ3)          // 35840
#define NSTG3 3
#define SMEM_TOTAL3 (NSTG3 * STAGE3)  // 107520 (x2 CTAs = 215KB <= 228KB)

__device__ __forceinline__ void cpasync16(uint32_t dst, const void* src) {
    asm volatile("cp.async.cg.shared.global [%0], [%1], 16;" :: "r"(dst), "l"(src));
}
__device__ __forceinline__ void ldsm4(uint32_t* r, uint32_t addr) {
    asm volatile("ldmatrix.sync.aligned.m8n8.x4.shared.b16 {%0,%1,%2,%3}, [%4];"
        : "=r"(r[0]), "=r"(r[1]), "=r"(r[2]), "=r"(r[3]) : "r"(addr));
}
__device__ __forceinline__ void ldsm4t(uint32_t* r, uint32_t addr) {
    asm volatile("ldmatrix.sync.aligned.m8n8.x4.trans.shared.b16 {%0,%1,%2,%3}, [%4];"
        : "=r"(r[0]), "=r"(r[1]), "=r"(r[2]), "=r"(r[3]) : "r"(addr));
}
#define MMA(acc, a, b) \
    asm volatile("mma.sync.aligned.m16n8k16.row.col.f32.f16.f16.f32 " \
        "{%0,%1,%2,%3}, {%4,%5,%6,%7}, {%8,%9}, {%0,%1,%2,%3};" \
        : "+f"((acc)[0]), "+f"((acc)[1]), "+f"((acc)[2]), "+f"((acc)[3]) \
        : "r"((a)[0]), "r"((a)[1]), "r"((a)[2]), "r"((a)[3]), \
          "r"((b)[0]), "r"((b)[1]))

__global__ void __launch_bounds__(128, 2) gemm_mma_kernel() {
    extern __shared__ __align__(128) char smem[];
    uint32_t sb = smem_u32(smem);
    int tid = threadIdx.x, wid = tid >> 5, lid = tid & 31;
    int rt = blockIdx.x, ct = blockIdx.y, ks = blockIdx.z;
    int warpM = (wid >> 1) * 64;        // 0 or 64
    int warpN = (wid & 1) * 64;         // 0 or 64

    const char* Ab = (const char*)g_A + ((size_t)rt * 128 * KK + (size_t)ks * KHALF) * 2;
    const char* Bb = (const char*)g_B + ((size_t)ks * KHALF * NT + (size_t)ct * 128) * 2;
    float* Aggp = ks ? g_Agg1 : g_Agg0;

    float acc[4][8][4];
    #pragma unroll
    for (int mi = 0; mi < 4; mi++)
        #pragma unroll
        for (int nj = 0; nj < 8; nj++)
            #pragma unroll
            for (int q = 0; q < 4; q++) acc[mi][nj][q] = 0.f;

    // ldmatrix per-lane address components
    int aRow = lid & 15, aK = lid >> 4;                        // A
    int bK = (lid & 7) + ((lid >> 3) & 1) * 8;                 // B (trans)
    int bN = ((lid >> 4) & 1) * 8;

    auto issue = [&](int s, int k0) {
        uint32_t d = sb + s * STAGE3;
        // A: 128 rows x 64 k = 1024 16B-chunks (8/thread)
        #pragma unroll
        for (int i = 0; i < 8; i++) {
            int ci = tid + i * 128;
            int ar = ci >> 3, ak = ci & 7;
            cpasync16(d + ar * APITCH3 + ak * 16,
                      Ab + ((size_t)ar * KK + k0 + ak * 8) * 2);
        }
        // B: 64 k-rows x 128 cols = 1024 16B-chunks (8/thread)
        #pragma unroll
        for (int i = 0; i < 8; i++) {
            int ci = tid + i * 128;
            int bk = ci >> 4, bc = ci & 15;
            cpasync16(d + BOFF3 + bk * BPITCH3 + bc * 16,
                      Bb + ((size_t)(k0 + bk) * NT + bc * 8) * 2);
        }
    };
    auto loadA = [&](uint32_t st, int k16, uint32_t (*a)[4]) {
        #pragma unroll
        for (int mi = 0; mi < 4; mi++)
            ldsm4(a[mi], st + (warpM + mi * 16 + aRow) * APITCH3 + k16 * 32 + aK * 16);
    };
    auto loadB = [&](uint32_t st, int k16, uint32_t (*b)[4]) {
        #pragma unroll
        for (int nb = 0; nb < 4; nb++)
            ldsm4t(b[nb], st + BOFF3 + (k16 * 16 + bK) * BPITCH3 + (warpN + nb * 16 + bN) * 2);
    };

    uint32_t a0[4][4], b0[4][4], a1[4][4], b1[4][4];

    // prologue: fill 2 stages, then preload (it=0, k16=0) fragments
    issue(0, 0);
    asm volatile("cp.async.commit_group;" ::: "memory");
    issue(1, 64);
    asm volatile("cp.async.commit_group;" ::: "memory");
    asm volatile("cp.async.wait_group 1;" ::: "memory");
    __syncthreads();
    loadA(sb, 0, a0);
    loadB(sb, 0, b0);

    int st_idx = 0;
    for (int it = 0; it < NIT3; it++) {
        uint32_t st = sb + st_idx * STAGE3;

        // k16 = 0: prefetch k16=1, MMA buf0
        loadA(st, 1, a1);
        loadB(st, 1, b1);
        #pragma unroll
        for (int mi = 0; mi < 4; mi++)
            #pragma unroll
            for (int nj = 0; nj < 8; nj++)
                MMA(acc[mi][nj], a0[mi], &b0[nj >> 1][(nj & 1) * 2]);

        // k16 = 1: prefetch k16=2, MMA buf1
        loadA(st, 2, a0);
        loadB(st, 2, b0);
        #pragma unroll
        for (int mi = 0; mi < 4; mi++)
            #pragma unroll
            for (int nj = 0; nj < 8; nj++)
                MMA(acc[mi][nj], a1[mi], &b1[nj >> 1][(nj & 1) * 2]);

        // k16 = 2: prefetch k16=3, MMA buf0
        loadA(st, 3, a1);
        loadB(st, 3, b1);
        #pragma unroll
        for (int mi = 0; mi < 4; mi++)
            #pragma unroll
            for (int nj = 0; nj < 8; nj++)
                MMA(acc[mi][nj], a0[mi], &b0[nj >> 1][(nj & 1) * 2]);

        // refill pipeline + advance; then MMA buf1 (k16 = 3)
        int nxt = it + 2;
        int nstage = st_idx + 2; if (nstage >= NSTG3) nstage -= NSTG3;
        if (nxt < NIT3) issue(nstage, nxt * 64);
        asm volatile("cp.async.commit_group;" ::: "memory");
        if (it + 1 < NIT3) {
            asm volatile("cp.async.wait_group 1;" ::: "memory");
            __syncthreads();
            int s1 = st_idx + 1; if (s1 >= NSTG3) s1 -= NSTG3;
            uint32_t stn = sb + s1 * STAGE3;
            loadA(stn, 0, a0);
            loadB(stn, 0, b0);
        }
        #pragma unroll
        for (int mi = 0; mi < 4; mi++)
            #pragma unroll
            for (int nj = 0; nj < 8; nj++)
                MMA(acc[mi][nj], a1[mi], &b1[nj >> 1][(nj & 1) * 2]);

        if (++st_idx >= NSTG3) st_idx = 0;
    }

    // epilogue: scale by rowinv, store partial
    #pragma unroll
    for (int mi = 0; mi < 4; mi++) {
        int r0 = rt * 128 + warpM + mi * 16 + (lid >> 2);
        int r1 = r0 + 8;
        float ri0 = (r0 < Nn) ? g_rowinv[r0] : 0.f;
        float ri1 = (r1 < Nn) ? g_rowinv[r1] : 0.f;
        #pragma unroll
        for (int nj = 0; nj < 8; nj++) {
            int n = ct * 128 + warpN + nj * 8 + (lid & 3) * 2;
            if (r0 < Nn) {
                float2 v = make_float2(acc[mi][nj][0] * ri0, acc[mi][nj][1] * ri0);
                *(float2*)&Aggp[(size_t)r0 * NT + n] = v;
            }
            if (r1 < Nn) {
                float2 v = make_float2(acc[mi][nj][2] * ri1, acc[mi][nj][3] * ri1);
                *(float2*)&Aggp[(size_t)r1 * NT + n] = v;
            }
        }
    }
}

// ---------------------------------------------------------------------------
// Kernel 3: epilogue. S = T0 + Agg0 + Agg1; E-weighted combine + biases,
// gates, final linear. No x re-read, no per-node weight rebuild.
// ---------------------------------------------------------------------------
__global__ void __launch_bounds__(128) epilogue_kernel(
    const float* __restrict__ E,
    const float* __restrict__ bgp, const float* __restrict__ bup,
    const float* __restrict__ lw, const float* __restrict__ lb,
    float* __restrict__ out)
{
    __shared__ float sBg[8][4];
    __shared__ float sBu[8][2];
    int n0 = blockIdx.x * 8;
    int tid = threadIdx.x;
    if (tid < 32) {
        int ln = tid >> 2, o = tid & 3; int n = n0 + ln; float v = 0.f;
        if (n < Nn) { for (int d = 0; d < 4; d++) v += E[n * 4 + d] * bgp[d * 4 + o]; }
        sBg[ln][o] = v;
    } else if (tid < 48) {
        int t = tid - 32, ln = t >> 1, o = t & 1; int n = n0 + ln; float v = 0.f;
        if (n < Nn) { for (int d = 0; d < 4; d++) v += E[n * 4 + d] * bup[d * 2 + o]; }
        sBu[ln][o] = v;
    }
    __syncthreads();

    int ln = tid >> 4, b = tid & 15;
    int n = n0 + ln;
    if (n >= Nn) return;
    float e0 = E[n * 4 + 0], e1 = E[n * 4 + 1], e2 = E[n * 4 + 2], e3 = E[n * 4 + 3];
    size_t base = (size_t)n * NT + b * 24;
    const float4* t0 = (const float4*)(g_T0 + base);
    const float4* g0 = (const float4*)(g_Agg0 + base);
    const float4* g1 = (const float4*)(g_Agg1 + base);
    float S[24];
    #pragma unroll
    for (int q = 0; q < 6; q++) {
        float4 a = t0[q], bq = g0[q], c = g1[q];
        S[q * 4 + 0] = a.x + bq.x + c.x;
        S[q * 4 + 1] = a.y + bq.y + c.y;
        S[q * 4 + 2] = a.z + bq.z + c.z;
        S[q * 4 + 3] = a.w + bq.w + c.w;
    }
    float go[4], uo[2];
    #pragma unroll
    for (int o = 0; o < 4; o++)
        go[o] = sBg[ln][o] + e0 * S[o] + e1 * S[6 + o] + e2 * S[12 + o] + e3 * S[18 + o];
    #pragma unroll
    for (int o = 0; o < 2; o++)
        uo[o] = sBu[ln][o] + e0 * S[4 + o] + e1 * S[10 + o] + e2 * S[16 + o] + e3 * S[22 + o];

    float R0 = 1.f / (1.f + __expf(-go[2]));
    float R1 = 1.f / (1.f + __expf(-go[3]));
    float C0 = tanhf(uo[0]);
    float C1 = tanhf(uo[1]);
    float h0 = (1.f - R0) * C0;
    float h1 = (1.f - R1) * C1;
    float y = fmaxf(h0, 0.f) * lw[0] + fmaxf(h1, 0.f) * lw[1] + lb[0];
    out[(size_t)b * Nn + n] = y;
}

// ---------------------------------------------------------------------------
extern "C" void kernel_launch(void* const* d_in, const int* in_sizes, int n_in,
                              void* d_out, int out_size) {
    const float* x  = (const float*)d_in[0];
    const float* e  = (const float*)d_in[1];
    const float* wg = (const float*)d_in[2];
    const float* bg = (const float*)d_in[3];
    const float* wu = (const float*)d_in[4];
    const float* bu = (const float*)d_in[5];
    const float* lw = (const float*)d_in[6];
    const float* lb = (const float*)d_in[7];
    float* out = (float*)d_out;

    cudaFuncSetAttribute(gemm_mma_kernel,
                         cudaFuncAttributeMaxDynamicSharedMemorySize, SMEM_TOTAL3);

    normmax_kernel<<<(Nn + 255) / 256, 256>>>(e);
    fused_prep_kernel<<<MP / 8 + (KK / 2) / 16, 256>>>(e, x, wg, wu);
    gemm_mma_kernel<<<dim3(MT, CT, 2), 128, SMEM_TOTAL3>>>();
    epilogue_kernel<<<(Nn + 7) / 8, 128>>>(e, bg, bu, lw, lb, out);
}

// round 14
// speedup vs baseline: 1.0411x; 1.0411x over previous
#include <cuda_runtime.h>
#include <cuda_fp16.h>
#include <cstdint>

// ---------------------------------------------------------------------------
// Problem constants
// ---------------------------------------------------------------------------
#define Nn 5570          // nodes
#define NT 384           // aggregation columns = B(16) * D(4) * 6
#define MP 5632          // M padded: 44 tiles of 128
#define KK 5632          // K padded
#define KHALF 2816       // K per z-slice
#define MT 44            // row tiles
#define CT 3             // col tiles (3 x 128 = 384)
#define NIT3 (KHALF / 64) // GEMM k-iterations per slice (44)

// ---------------------------------------------------------------------------
// Device scratch
// ---------------------------------------------------------------------------
__device__ __align__(128) uint32_t g_A[(size_t)MP * KK / 2];
__device__ __align__(128) uint32_t g_B[(size_t)KK * NT / 2];
__device__ float g_T0[(size_t)KK * NT];     // k=0 (identity) per-node partials
__device__ float g_rowinv[MP];
__device__ float g_Agg0[(size_t)MP * NT];   // K-half 0 partial (rowinv applied)
__device__ float g_Agg1[(size_t)MP * NT];   // K-half 1 partial (rowinv applied)
__device__ unsigned int g_gmax2_bits = 0u;  // max_m |e_m|^2 bits (atomicMax is
                                            // idempotent across graph replays)

// ---------------------------------------------------------------------------
// Helpers
// ---------------------------------------------------------------------------
__device__ __forceinline__ uint32_t smem_u32(const void* p) {
    uint32_t a;
    asm("{ .reg .u64 t; cvta.to.shared.u64 t, %1; cvt.u32.u64 %0, t; }" : "=r"(a) : "l"(p));
    return a;
}

// Fast exp on the FMA pipe for arg <= 0, arg >= -90. ~4e-5 relative error.
__device__ __forceinline__ float fexpn(float arg) {
    float t = arg * 1.4426950408889634f;
    float km = t + 12582912.0f;                 // round-to-nearest magic
    int   ki = __float_as_int(km);
    float f  = t - (km - 12582912.0f);          // f in [-0.5, 0.5]
    float p  = 9.6180691e-3f;
    p = fmaf(p, f, 5.5504109e-2f);
    p = fmaf(p, f, 2.4022651e-1f);
    p = fmaf(p, f, 6.9314718e-1f);
    p = fmaf(p, f, 1.0f);
    float sc = __int_as_float((ki - (0x4B400000 - 127)) << 23);  // 2^round(t)
    return p * sc;
}

// ---------------------------------------------------------------------------
// Micro-kernel: global max of |e_m|^2
// ---------------------------------------------------------------------------
__global__ void __launch_bounds__(256) normmax_kernel(const float* __restrict__ E) {
    int m = blockIdx.x * 256 + threadIdx.x;
    float v = 0.f;
    if (m < Nn) {
        float4 em = ((const float4*)E)[m];
        v = fmaf(em.x, em.x, fmaf(em.y, em.y, fmaf(em.z, em.z, em.w * em.w)));
    }
    #pragma unroll
    for (int o = 16; o > 0; o >>= 1) v = fmaxf(v, __shfl_xor_sync(0xffffffffu, v, o));
    if ((threadIdx.x & 31) == 0)
        atomicMax(&g_gmax2_bits, __float_as_uint(v));  // positive floats: uint order
}

// ---------------------------------------------------------------------------
// Kernel 1 (fused): blocks [0, 704): bounded-softmax P -> fp16 (single pass).
//                   blocks [704, 1056): T^T (k=1 -> fp16 B) and T0 (k=0 -> fp32),
//                   ONE m-row per thread (48 accumulators, keeps regs low).
// ---------------------------------------------------------------------------
__global__ void __launch_bounds__(256) fused_prep_kernel(
    const float* __restrict__ E, const float* __restrict__ x,
    const float* __restrict__ wg, const float* __restrict__ wu)
{
    int tid = threadIdx.x;
    if (blockIdx.x < MP / 8) {
        // ---------------- exp part: one warp per row, single pass -------------
        int row  = blockIdx.x * 8 + (tid >> 5);
        int lane = tid & 31;
        const float4* E4 = (const float4*)E;
        bool valid = (row < Nn);
        float4 en = make_float4(0.f, 0.f, 0.f, 0.f);
        if (valid) en = E4[row];
        float en2 = fmaf(en.x, en.x, fmaf(en.y, en.y, fmaf(en.z, en.z, en.w * en.w)));
        float gmax2 = __uint_as_float(g_gmax2_bits);
        // Cauchy-Schwarz bound: M >= max_m en.em  (em includes en => M >= en2 >= 0)
        float M = sqrtf(en2 * gmax2);

        size_t rbase = (size_t)row * (KK / 2);
        float sum = 0.f;
        for (int kc = 0; kc < KK / 64; kc++) {
            int k0 = kc * 64 + lane * 2;
            float p0 = 0.f, p1 = 0.f;
            if (valid && k0 < Nn) {
                float4 e0 = __ldg(&E4[k0]);
                float4 e1 = __ldg(&E4[k0 + 1]);
                float z0 = fmaf(en.x, e0.x, fmaf(en.y, e0.y, fmaf(en.z, e0.z, en.w * e0.w)));
                float z1 = fmaf(en.x, e1.x, fmaf(en.y, e1.y, fmaf(en.z, e1.z, en.w * e1.w)));
                p0 = fexpn(fmaxf(z0, 0.f) - M);
                p1 = fexpn(fmaxf(z1, 0.f) - M);
            }
            sum += p0 + p1;
            __half2 h = __floats2half2_rn(p0, p1);
            g_A[rbase + kc * 32 + lane] = *reinterpret_cast<uint32_t*>(&h);
        }
        #pragma unroll
        for (int o = 16; o > 0; o >>= 1) sum += __shfl_xor_sync(0xffffffffu, sum, o);
        if (valid && lane == 0) g_rowinv[row] = 1.f / sum;
    } else {
        // -------- T parts: 16 m-rows x 16 batches per block, k=1 and k=0 -------
        __shared__ float sW1[35][24];  // [i][d*6+o], k=1 support weights
        __shared__ float sW0[35][24];  // [i][d*6+o], k=0 (identity) weights
        for (int idx = tid; idx < 35 * 24; idx += 256) {
            int i = idx / 24, j = idx % 24, d = j / 6, o = j % 6;
            sW1[i][j] = (o < 4) ? wg[((d * 2 + 1) * 37 + i) * 4 + o]
                                : wu[((d * 2 + 1) * 37 + i) * 2 + (o - 4)];
            sW0[i][j] = (o < 4) ? wg[((d * 2) * 37 + i) * 4 + o]
                                : wu[((d * 2) * 37 + i) * 2 + (o - 4)];
        }
        __syncthreads();
        int bb = blockIdx.x - MP / 8;
        int m = bb * 16 + (tid >> 4);   // m-row (0..5631)
        int b = tid & 15;
        float ak[24], az[24];           // k=1 and k=0 accumulators
        #pragma unroll
        for (int j = 0; j < 24; j++) { ak[j] = 0.f; az[j] = 0.f; }
        if (m < Nn) {
            const float* xp = x + ((size_t)b * Nn + m) * 35;
            for (int i = 0; i < 35; i++) {
                float xv = xp[i];
                #pragma unroll
                for (int j = 0; j < 24; j++) {
                    ak[j] = fmaf(xv, sW1[i][j], ak[j]);
                    az[j] = fmaf(xv, sW0[i][j], az[j]);
                }
            }
        }
        size_t baseB = (size_t)m * (NT / 2) + b * 12;
        #pragma unroll
        for (int j = 0; j < 12; j++) {
            __half2 h = __floats2half2_rn(ak[2 * j], ak[2 * j + 1]);
            g_B[baseB + j] = *reinterpret_cast<uint32_t*>(&h);
        }
        float* t0p = g_T0 + (size_t)m * NT + b * 24;
        #pragma unroll
        for (int j = 0; j < 6; j++) {
            float4 v = make_float4(az[4 * j], az[4 * j + 1], az[4 * j + 2], az[4 * j + 3]);
            *(float4*)&t0p[4 * j] = v;
        }
    }
}

// ---------------------------------------------------------------------------
// Kernel 2: GEMM partials Agg[z] = rowinv * (P[:, zK:zK+2816] @ T[zK:...]).
// Grid (44, 3, 2); CTA 128x128xKHALF, 4 warps (64x64 tiles), BK=64,
// 3-stage cp.async pipeline + register double-buffering at k16 granularity.
// 2 CTAs/SM (uncorrelated barriers). A pitch 144, B pitch 272 (conflict-free).
// ---------------------------------------------------------------------------
#define APITCH3 144
#define BPITCH3 272
#define ASZ3 (128 * APITCH3)          // 18432
#define BSZ3 (64 * BPITCH3)           // 17408
#define BOFF3 ASZ3
#define STAGE3 (ASZ3 + BSZ3)          // 35840
#define NSTG3 3
#define SMEM_TOTAL3 (NSTG3 * STAGE3)  // 107520 (x2 CTAs = 215KB <= 228KB)

__device__ __forceinline__ void cpasync16(uint32_t dst, const void* src) {
    asm volatile("cp.async.cg.shared.global [%0], [%1], 16;" :: "r"(dst), "l"(src));
}
__device__ __forceinline__ void ldsm4(uint32_t* r, uint32_t addr) {
    asm volatile("ldmatrix.sync.aligned.m8n8.x4.shared.b16 {%0,%1,%2,%3}, [%4];"
        : "=r"(r[0]), "=r"(r[1]), "=r"(r[2]), "=r"(r[3]) : "r"(addr));
}
__device__ __forceinline__ void ldsm4t(uint32_t* r, uint32_t addr) {
    asm volatile("ldmatrix.sync.aligned.m8n8.x4.trans.shared.b16 {%0,%1,%2,%3}, [%4];"
        : "=r"(r[0]), "=r"(r[1]), "=r"(r[2]), "=r"(r[3]) : "r"(addr));
}
#define MMA(acc, a, b) \
    asm volatile("mma.sync.aligned.m16n8k16.row.col.f32.f16.f16.f32 " \
        "{%0,%1,%2,%3}, {%4,%5,%6,%7}, {%8,%9}, {%0,%1,%2,%3};" \
        : "+f"((acc)[0]), "+f"((acc)[1]), "+f"((acc)[2]), "+f"((acc)[3]) \
        : "r"((a)[0]), "r"((a)[1]), "r"((a)[2]), "r"((a)[3]), \
          "r"((b)[0]), "r"((b)[1]))

__global__ void __launch_bounds__(128, 2) gemm_mma_kernel() {
    extern __shared__ __align__(128) char smem[];
    uint32_t sb = smem_u32(smem);
    int tid = threadIdx.x, wid = tid >> 5, lid = tid & 31;
    int rt = blockIdx.x, ct = blockIdx.y, ks = blockIdx.z;
    int warpM = (wid >> 1) * 64;        // 0 or 64
    int warpN = (wid & 1) * 64;         // 0 or 64

    const char* Ab = (const char*)g_A + ((size_t)rt * 128 * KK + (size_t)ks * KHALF) * 2;
    const char* Bb = (const char*)g_B + ((size_t)ks * KHALF * NT + (size_t)ct * 128) * 2;
    float* Aggp = ks ? g_Agg1 : g_Agg0;

    float acc[4][8][4];
    #pragma unroll
    for (int mi = 0; mi < 4; mi++)
        #pragma unroll
        for (int nj = 0; nj < 8; nj++)
            #pragma unroll
            for (int q = 0; q < 4; q++) acc[mi][nj][q] = 0.f;

    // ldmatrix per-lane address components
    int aRow = lid & 15, aK = lid >> 4;                        // A
    int bK = (lid & 7) + ((lid >> 3) & 1) * 8;                 // B (trans)
    int bN = ((lid >> 4) & 1) * 8;

    auto issue = [&](int s, int k0) {
        uint32_t d = sb + s * STAGE3;
        // A: 128 rows x 64 k = 1024 16B-chunks (8/thread)
        #pragma unroll
        for (int i = 0; i < 8; i++) {
            int ci = tid + i * 128;
            int ar = ci >> 3, ak = ci & 7;
            cpasync16(d + ar * APITCH3 + ak * 16,
                      Ab + ((size_t)ar * KK + k0 + ak * 8) * 2);
        }
        // B: 64 k-rows x 128 cols = 1024 16B-chunks (8/thread)
        #pragma unroll
        for (int i = 0; i < 8; i++) {
            int ci = tid + i * 128;
            int bk = ci >> 4, bc = ci & 15;
            cpasync16(d + BOFF3 + bk * BPITCH3 + bc * 16,
                      Bb + ((size_t)(k0 + bk) * NT + bc * 8) * 2);
        }
    };
    auto loadA = [&](uint32_t st, int k16, uint32_t (*a)[4]) {
        #pragma unroll
        for (int mi = 0; mi < 4; mi++)
            ldsm4(a[mi], st + (warpM + mi * 16 + aRow) * APITCH3 + k16 * 32 + aK * 16);
    };
    auto loadB = [&](uint32_t st, int k16, uint32_t (*b)[4]) {
        #pragma unroll
        for (int nb = 0; nb < 4; nb++)
            ldsm4t(b[nb], st + BOFF3 + (k16 * 16 + bK) * BPITCH3 + (warpN + nb * 16 + bN) * 2);
    };

    uint32_t a0[4][4], b0[4][4], a1[4][4], b1[4][4];

    // prologue: fill 2 stages, then preload (it=0, k16=0) fragments
    issue(0, 0);
    asm volatile("cp.async.commit_group;" ::: "memory");
    issue(1, 64);
    asm volatile("cp.async.commit_group;" ::: "memory");
    asm volatile("cp.async.wait_group 1;" ::: "memory");
    __syncthreads();
    loadA(sb, 0, a0);
    loadB(sb, 0, b0);

    int st_idx = 0;
    for (int it = 0; it < NIT3; it++) {
        uint32_t st = sb + st_idx * STAGE3;

        // k16 = 0: prefetch k16=1, MMA buf0
        loadA(st, 1, a1);
        loadB(st, 1, b1);
        #pragma unroll
        for (int mi = 0; mi < 4; mi++)
            #pragma unroll
            for (int nj = 0; nj < 8; nj++)
                MMA(acc[mi][nj], a0[mi], &b0[nj >> 1][(nj & 1) * 2]);

        // k16 = 1: prefetch k16=2, MMA buf1
        loadA(st, 2, a0);
        loadB(st, 2, b0);
        #pragma unroll
        for (int mi = 0; mi < 4; mi++)
            #pragma unroll
            for (int nj = 0; nj < 8; nj++)
                MMA(acc[mi][nj], a1[mi], &b1[nj >> 1][(nj & 1) * 2]);

        // k16 = 2: prefetch k16=3, MMA buf0
        loadA(st, 3, a1);
        loadB(st, 3, b1);
        #pragma unroll
        for (int mi = 0; mi < 4; mi++)
            #pragma unroll
            for (int nj = 0; nj < 8; nj++)
                MMA(acc[mi][nj], a0[mi], &b0[nj >> 1][(nj & 1) * 2]);

        // refill pipeline + advance; then MMA buf1 (k16 = 3)
        int nxt = it + 2;
        int nstage = st_idx + 2; if (nstage >= NSTG3) nstage -= NSTG3;
        if (nxt < NIT3) issue(nstage, nxt * 64);
        asm volatile("cp.async.commit_group;" ::: "memory");
        if (it + 1 < NIT3) {
            asm volatile("cp.async.wait_group 1;" ::: "memory");
            __syncthreads();
            int s1 = st_idx + 1; if (s1 >= NSTG3) s1 -= NSTG3;
            uint32_t stn = sb + s1 * STAGE3;
            loadA(stn, 0, a0);
            loadB(stn, 0, b0);
        }
        #pragma unroll
        for (int mi = 0; mi < 4; mi++)
            #pragma unroll
            for (int nj = 0; nj < 8; nj++)
                MMA(acc[mi][nj], a1[mi], &b1[nj >> 1][(nj & 1) * 2]);

        if (++st_idx >= NSTG3) st_idx = 0;
    }

    // epilogue: scale by rowinv, store partial
    #pragma unroll
    for (int mi = 0; mi < 4; mi++) {
        int r0 = rt * 128 + warpM + mi * 16 + (lid >> 2);
        int r1 = r0 + 8;
        float ri0 = (r0 < Nn) ? g_rowinv[r0] : 0.f;
        float ri1 = (r1 < Nn) ? g_rowinv[r1] : 0.f;
        #pragma unroll
        for (int nj = 0; nj < 8; nj++) {
            int n = ct * 128 + warpN + nj * 8 + (lid & 3) * 2;
            if (r0 < Nn) {
                float2 v = make_float2(acc[mi][nj][0] * ri0, acc[mi][nj][1] * ri0);
                *(float2*)&Aggp[(size_t)r0 * NT + n] = v;
            }
            if (r1 < Nn) {
                float2 v = make_float2(acc[mi][nj][2] * ri1, acc[mi][nj][3] * ri1);
                *(float2*)&Aggp[(size_t)r1 * NT + n] = v;
            }
        }
    }
}

// ---------------------------------------------------------------------------
// Kernel 3: epilogue. S = T0 + Agg0 + Agg1; E-weighted combine + biases,
// gates, final linear. No x re-read, no per-node weight rebuild.
// ---------------------------------------------------------------------------
__global__ void __launch_bounds__(128) epilogue_kernel(
    const float* __restrict__ E,
    const float* __restrict__ bgp, const float* __restrict__ bup,
    const float* __restrict__ lw, const float* __restrict__ lb,
    float* __restrict__ out)
{
    __shared__ float sBg[8][4];
    __shared__ float sBu[8][2];
    int n0 = blockIdx.x * 8;
    int tid = threadIdx.x;
    if (tid < 32) {
        int ln = tid >> 2, o = tid & 3; int n = n0 + ln; float v = 0.f;
        if (n < Nn) { for (int d = 0; d < 4; d++) v += E[n * 4 + d] * bgp[d * 4 + o]; }
        sBg[ln][o] = v;
    } else if (tid < 48) {
        int t = tid - 32, ln = t >> 1, o = t & 1; int n = n0 + ln; float v = 0.f;
        if (n < Nn) { for (int d = 0; d < 4; d++) v += E[n * 4 + d] * bup[d * 2 + o]; }
        sBu[ln][o] = v;
    }
    __syncthreads();

    int ln = tid >> 4, b = tid & 15;
    int n = n0 + ln;
    if (n >= Nn) return;
    float e0 = E[n * 4 + 0], e1 = E[n * 4 + 1], e2 = E[n * 4 + 2], e3 = E[n * 4 + 3];
    size_t base = (size_t)n * NT + b * 24;
    const float4* t0 = (const float4*)(g_T0 + base);
    const float4* g0 = (const float4*)(g_Agg0 + base);
    const float4* g1 = (const float4*)(g_Agg1 + base);
    float S[24];
    #pragma unroll
    for (int q = 0; q < 6; q++) {
        float4 a = t0[q], bq = g0[q], c = g1[q];
        S[q * 4 + 0] = a.x + bq.x + c.x;
        S[q * 4 + 1] = a.y + bq.y + c.y;
        S[q * 4 + 2] = a.z + bq.z + c.z;
        S[q * 4 + 3] = a.w + bq.w + c.w;
    }
    float go[4], uo[2];
    #pragma unroll
    for (int o = 0; o < 4; o++)
        go[o] = sBg[ln][o] + e0 * S[o] + e1 * S[6 + o] + e2 * S[12 + o] + e3 * S[18 + o];
    #pragma unroll
    for (int o = 0; o < 2; o++)
        uo[o] = sBu[ln][o] + e0 * S[4 + o] + e1 * S[10 + o] + e2 * S[16 + o] + e3 * S[22 + o];

    float R0 = 1.f / (1.f + __expf(-go[2]));
    float R1 = 1.f / (1.f + __expf(-go[3]));
    float C0 = tanhf(uo[0]);
    float C1 = tanhf(uo[1]);
    float h0 = (1.f - R0) * C0;
    float h1 = (1.f - R1) * C1;
    float y = fmaxf(h0, 0.f) * lw[0] + fmaxf(h1, 0.f) * lw[1] + lb[0];
    out[(size_t)b * Nn + n] = y;
}

// ---------------------------------------------------------------------------
extern "C" void kernel_launch(void* const* d_in, const int* in_sizes, int n_in,
                              void* d_out, int out_size) {
    const float* x  = (const float*)d_in[0];
    const float* e  = (const float*)d_in[1];
    const float* wg = (const float*)d_in[2];
    const float* bg = (const float*)d_in[3];
    const float* wu = (const float*)d_in[4];
    const float* bu = (const float*)d_in[5];
    const float* lw = (const float*)d_in[6];
    const float* lb = (const float*)d_in[7];
    float* out = (float*)d_out;

    cudaFuncSetAttribute(gemm_mma_kernel,
                         cudaFuncAttributeMaxDynamicSharedMemorySize, SMEM_TOTAL3);

    normmax_kernel<<<(Nn + 255) / 256, 256>>>(e);
    fused_prep_kernel<<<MP / 8 + KK / 16, 256>>>(e, x, wg, wu);
    gemm_mma_kernel<<<dim3(MT, CT, 2), 128, SMEM_TOTAL3>>>();
    epilogue_kernel<<<(Nn + 7) / 8, 128>>>(e, bg, bu, lw, lb, out);
}

// round 15
// speedup vs baseline: 1.1102x; 1.0664x over previous
#include <cuda_runtime.h>
#include <cuda_fp16.h>
#include <cstdint>

// ---------------------------------------------------------------------------
// Problem constants
// ---------------------------------------------------------------------------
#define Nn 5570          // nodes
#define NT 256           // live aggregation columns = B(16) * D(4) * 4 (Z dropped)
#define MP 5632          // M padded: 44 tiles of 128
#define KK 5632          // K padded
#define KHALF 2816       // K per z-slice
#define MT 44            // row tiles
#define CT 2             // col tiles (2 x 128 = 256)
#define NIT3 (KHALF / 64) // GEMM k-iterations per slice (44)

// ---------------------------------------------------------------------------
// Device scratch
// Column layout (per m/n row): j = b*16 + d*4 + o,
//   o in {0,1} -> R gate outputs (original gate cols 2,3)
//   o in {2,3} -> C update outputs (original update cols 0,1)
// ---------------------------------------------------------------------------
__device__ __align__(128) uint32_t g_A[(size_t)MP * KK / 2];
__device__ __align__(128) uint32_t g_B[(size_t)KK * NT / 2];
__device__ float g_T0[(size_t)KK * NT];     // k=0 (identity) per-node partials
__device__ float g_rowinv[MP];
__device__ float g_Agg0[(size_t)MP * NT];   // K-half 0 partial (rowinv applied)
__device__ float g_Agg1[(size_t)MP * NT];   // K-half 1 partial (rowinv applied)
__device__ unsigned int g_gmax2_bits = 0u;  // max_m |e_m|^2 bits (atomicMax is
                                            // idempotent across graph replays)

// ---------------------------------------------------------------------------
// Helpers
// ---------------------------------------------------------------------------
__device__ __forceinline__ uint32_t smem_u32(const void* p) {
    uint32_t a;
    asm("{ .reg .u64 t; cvta.to.shared.u64 t, %1; cvt.u32.u64 %0, t; }" : "=r"(a) : "l"(p));
    return a;
}

// Fast exp on the FMA pipe for arg <= 0, arg >= -90. ~4e-5 relative error.
__device__ __forceinline__ float fexpn(float arg) {
    float t = arg * 1.4426950408889634f;
    float km = t + 12582912.0f;                 // round-to-nearest magic
    int   ki = __float_as_int(km);
    float f  = t - (km - 12582912.0f);          // f in [-0.5, 0.5]
    float p  = 9.6180691e-3f;
    p = fmaf(p, f, 5.5504109e-2f);
    p = fmaf(p, f, 2.4022651e-1f);
    p = fmaf(p, f, 6.9314718e-1f);
    p = fmaf(p, f, 1.0f);
    float sc = __int_as_float((ki - (0x4B400000 - 127)) << 23);  // 2^round(t)
    return p * sc;
}

// ---------------------------------------------------------------------------
// Micro-kernel: global max of |e_m|^2
// ---------------------------------------------------------------------------
__global__ void __launch_bounds__(256) normmax_kernel(const float* __restrict__ E) {
    int m = blockIdx.x * 256 + threadIdx.x;
    float v = 0.f;
    if (m < Nn) {
        float4 em = ((const float4*)E)[m];
        v = fmaf(em.x, em.x, fmaf(em.y, em.y, fmaf(em.z, em.z, em.w * em.w)));
    }
    #pragma unroll
    for (int o = 16; o > 0; o >>= 1) v = fmaxf(v, __shfl_xor_sync(0xffffffffu, v, o));
    if ((threadIdx.x & 31) == 0)
        atomicMax(&g_gmax2_bits, __float_as_uint(v));  // positive floats: uint order
}

// ---------------------------------------------------------------------------
// Kernel 1 (fused): blocks [0, 704): bounded-softmax P -> fp16 (single pass).
//                   blocks [704, 1056): T^T (k=1 -> fp16 B) and T0 (k=0 -> fp32),
//                   one m-row per thread, 16 live columns per support.
// ---------------------------------------------------------------------------
__global__ void __launch_bounds__(256) fused_prep_kernel(
    const float* __restrict__ E, const float* __restrict__ x,
    const float* __restrict__ wg, const float* __restrict__ wu)
{
    int tid = threadIdx.x;
    if (blockIdx.x < MP / 8) {
        // ---------------- exp part: one warp per row, single pass -------------
        int row  = blockIdx.x * 8 + (tid >> 5);
        int lane = tid & 31;
        const float4* E4 = (const float4*)E;
        bool valid = (row < Nn);
        float4 en = make_float4(0.f, 0.f, 0.f, 0.f);
        if (valid) en = E4[row];
        float en2 = fmaf(en.x, en.x, fmaf(en.y, en.y, fmaf(en.z, en.z, en.w * en.w)));
        float gmax2 = __uint_as_float(g_gmax2_bits);
        // Cauchy-Schwarz bound: M >= max_m en.em  (em includes en => M >= en2 >= 0)
        float M = sqrtf(en2 * gmax2);

        size_t rbase = (size_t)row * (KK / 2);
        float sum = 0.f;
        for (int kc = 0; kc < KK / 64; kc++) {
            int k0 = kc * 64 + lane * 2;
            float p0 = 0.f, p1 = 0.f;
            if (valid && k0 < Nn) {
                float4 e0 = __ldg(&E4[k0]);
                float4 e1 = __ldg(&E4[k0 + 1]);
                float z0 = fmaf(en.x, e0.x, fmaf(en.y, e0.y, fmaf(en.z, e0.z, en.w * e0.w)));
                float z1 = fmaf(en.x, e1.x, fmaf(en.y, e1.y, fmaf(en.z, e1.z, en.w * e1.w)));
                p0 = fexpn(fmaxf(z0, 0.f) - M);
                p1 = fexpn(fmaxf(z1, 0.f) - M);
            }
            sum += p0 + p1;
            __half2 h = __floats2half2_rn(p0, p1);
            g_A[rbase + kc * 32 + lane] = *reinterpret_cast<uint32_t*>(&h);
        }
        #pragma unroll
        for (int o = 16; o > 0; o >>= 1) sum += __shfl_xor_sync(0xffffffffu, sum, o);
        if (valid && lane == 0) g_rowinv[row] = 1.f / sum;
    } else {
        // -------- T parts: 16 m-rows x 16 batches per block, live cols only ----
        // j = d*4 + o: o<2 -> gate col (o+2) [R], o>=2 -> update col (o-2) [C]
        __shared__ float sW1[35][16];  // k=1 support weights
        __shared__ float sW0[35][16];  // k=0 (identity) weights
        for (int idx = tid; idx < 35 * 16; idx += 256) {
            int i = idx / 16, j = idx % 16, d = j / 4, o = j % 4;
            sW1[i][j] = (o < 2) ? wg[((d * 2 + 1) * 37 + i) * 4 + (o + 2)]
                                : wu[((d * 2 + 1) * 37 + i) * 2 + (o - 2)];
            sW0[i][j] = (o < 2) ? wg[((d * 2) * 37 + i) * 4 + (o + 2)]
                                : wu[((d * 2) * 37 + i) * 2 + (o - 2)];
        }
        __syncthreads();
        int bb = blockIdx.x - MP / 8;
        int m = bb * 16 + (tid >> 4);   // m-row (0..5631)
        int b = tid & 15;
        float ak[16], az[16];           // k=1 and k=0 accumulators
        #pragma unroll
        for (int j = 0; j < 16; j++) { ak[j] = 0.f; az[j] = 0.f; }
        if (m < Nn) {
            const float* xp = x + ((size_t)b * Nn + m) * 35;
            for (int i = 0; i < 35; i++) {
                float xv = xp[i];
                #pragma unroll
                for (int j = 0; j < 16; j++) {
                    ak[j] = fmaf(xv, sW1[i][j], ak[j]);
                    az[j] = fmaf(xv, sW0[i][j], az[j]);
                }
            }
        }
        size_t baseB = (size_t)m * (NT / 2) + b * 8;
        #pragma unroll
        for (int j = 0; j < 8; j++) {
            __half2 h = __floats2half2_rn(ak[2 * j], ak[2 * j + 1]);
            g_B[baseB + j] = *reinterpret_cast<uint32_t*>(&h);
        }
        float* t0p = g_T0 + (size_t)m * NT + b * 16;
        #pragma unroll
        for (int j = 0; j < 4; j++) {
            float4 v = make_float4(az[4 * j], az[4 * j + 1], az[4 * j + 2], az[4 * j + 3]);
            *(float4*)&t0p[4 * j] = v;
        }
    }
}

// ---------------------------------------------------------------------------
// Kernel 2: GEMM partials Agg[z] = rowinv * (P[:, zK:zK+2816] @ T[zK:...]).
// Grid (44, 2, 2); CTA 128x128xKHALF, 4 warps (64x64 tiles), BK=64,
// 3-stage cp.async pipeline + register double-buffering at k16 granularity.
// 2 CTAs/SM (uncorrelated barriers). A pitch 144, B pitch 272 (conflict-free).
// ---------------------------------------------------------------------------
#define APITCH3 144
#define BPITCH3 272
#define ASZ3 (128 * APITCH3)          // 18432
#define BSZ3 (64 * BPITCH3)           // 17408
#define BOFF3 ASZ3
#define STAGE3 (ASZ3 + BSZ3)          // 35840
#define NSTG3 3
#define SMEM_TOTAL3 (NSTG3 * STAGE3)  // 107520 (x2 CTAs = 215KB <= 228KB)

__device__ __forceinline__ void cpasync16(uint32_t dst, const void* src) {
    asm volatile("cp.async.cg.shared.global [%0], [%1], 16;" :: "r"(dst), "l"(src));
}
__device__ __forceinline__ void ldsm4(uint32_t* r, uint32_t addr) {
    asm volatile("ldmatrix.sync.aligned.m8n8.x4.shared.b16 {%0,%1,%2,%3}, [%4];"
        : "=r"(r[0]), "=r"(r[1]), "=r"(r[2]), "=r"(r[3]) : "r"(addr));
}
__device__ __forceinline__ void ldsm4t(uint32_t* r, uint32_t addr) {
    asm volatile("ldmatrix.sync.aligned.m8n8.x4.trans.shared.b16 {%0,%1,%2,%3}, [%4];"
        : "=r"(r[0]), "=r"(r[1]), "=r"(r[2]), "=r"(r[3]) : "r"(addr));
}
#define MMA(acc, a, b) \
    asm volatile("mma.sync.aligned.m16n8k16.row.col.f32.f16.f16.f32 " \
        "{%0,%1,%2,%3}, {%4,%5,%6,%7}, {%8,%9}, {%0,%1,%2,%3};" \
        : "+f"((acc)[0]), "+f"((acc)[1]), "+f"((acc)[2]), "+f"((acc)[3]) \
        : "r"((a)[0]), "r"((a)[1]), "r"((a)[2]), "r"((a)[3]), \
          "r"((b)[0]), "r"((b)[1]))

__global__ void __launch_bounds__(128, 2) gemm_mma_kernel() {
    extern __shared__ __align__(128) char smem[];
    uint32_t sb = smem_u32(smem);
    int tid = threadIdx.x, wid = tid >> 5, lid = tid & 31;
    int rt = blockIdx.x, ct = blockIdx.y, ks = blockIdx.z;
    int warpM = (wid >> 1) * 64;        // 0 or 64
    int warpN = (wid & 1) * 64;         // 0 or 64

    const char* Ab = (const char*)g_A + ((size_t)rt * 128 * KK + (size_t)ks * KHALF) * 2;
    const char* Bb = (const char*)g_B + ((size_t)ks * KHALF * NT + (size_t)ct * 128) * 2;
    float* Aggp = ks ? g_Agg1 : g_Agg0;

    float acc[4][8][4];
    #pragma unroll
    for (int mi = 0; mi < 4; mi++)
        #pragma unroll
        for (int nj = 0; nj < 8; nj++)
            #pragma unroll
            for (int q = 0; q < 4; q++) acc[mi][nj][q] = 0.f;

    // ldmatrix per-lane address components
    int aRow = lid & 15, aK = lid >> 4;                        // A
    int bK = (lid & 7) + ((lid >> 3) & 1) * 8;                 // B (trans)
    int bN = ((lid >> 4) & 1) * 8;

    auto issue = [&](int s, int k0) {
        uint32_t d = sb + s * STAGE3;
        // A: 128 rows x 64 k = 1024 16B-chunks (8/thread)
        #pragma unroll
        for (int i = 0; i < 8; i++) {
            int ci = tid + i * 128;
            int ar = ci >> 3, ak = ci & 7;
            cpasync16(d + ar * APITCH3 + ak * 16,
                      Ab + ((size_t)ar * KK + k0 + ak * 8) * 2);
        }
        // B: 64 k-rows x 128 cols = 1024 16B-chunks (8/thread)
        #pragma unroll
        for (int i = 0; i < 8; i++) {
            int ci = tid + i * 128;
            int bk = ci >> 4, bc = ci & 15;
            cpasync16(d + BOFF3 + bk * BPITCH3 + bc * 16,
                      Bb + ((size_t)(k0 + bk) * NT + bc * 8) * 2);
        }
    };
    auto loadA = [&](uint32_t st, int k16, uint32_t (*a)[4]) {
        #pragma unroll
        for (int mi = 0; mi < 4; mi++)
            ldsm4(a[mi], st + (warpM + mi * 16 + aRow) * APITCH3 + k16 * 32 + aK * 16);
    };
    auto loadB = [&](uint32_t st, int k16, uint32_t (*b)[4]) {
        #pragma unroll
        for (int nb = 0; nb < 4; nb++)
            ldsm4t(b[nb], st + BOFF3 + (k16 * 16 + bK) * BPITCH3 + (warpN + nb * 16 + bN) * 2);
    };

    uint32_t a0[4][4], b0[4][4], a1[4][4], b1[4][4];

    // prologue: fill 2 stages, then preload (it=0, k16=0) fragments
    issue(0, 0);
    asm volatile("cp.async.commit_group;" ::: "memory");
    issue(1, 64);
    asm volatile("cp.async.commit_group;" ::: "memory");
    asm volatile("cp.async.wait_group 1;" ::: "memory");
    __syncthreads();
    loadA(sb, 0, a0);
    loadB(sb, 0, b0);

    int st_idx = 0;
    for (int it = 0; it < NIT3; it++) {
        uint32_t st = sb + st_idx * STAGE3;

        // k16 = 0: prefetch k16=1, MMA buf0
        loadA(st, 1, a1);
        loadB(st, 1, b1);
        #pragma unroll
        for (int mi = 0; mi < 4; mi++)
            #pragma unroll
            for (int nj = 0; nj < 8; nj++)
                MMA(acc[mi][nj], a0[mi], &b0[nj >> 1][(nj & 1) * 2]);

        // k16 = 1: prefetch k16=2, MMA buf1
        loadA(st, 2, a0);
        loadB(st, 2, b0);
        #pragma unroll
        for (int mi = 0; mi < 4; mi++)
            #pragma unroll
            for (int nj = 0; nj < 8; nj++)
                MMA(acc[mi][nj], a1[mi], &b1[nj >> 1][(nj & 1) * 2]);

        // k16 = 2: prefetch k16=3, MMA buf0
        loadA(st, 3, a1);
        loadB(st, 3, b1);
        #pragma unroll
        for (int mi = 0; mi < 4; mi++)
            #pragma unroll
            for (int nj = 0; nj < 8; nj++)
                MMA(acc[mi][nj], a0[mi], &b0[nj >> 1][(nj & 1) * 2]);

        // refill pipeline + advance; then MMA buf1 (k16 = 3)
        int nxt = it + 2;
        int nstage = st_idx + 2; if (nstage >= NSTG3) nstage -= NSTG3;
        if (nxt < NIT3) issue(nstage, nxt * 64);
        asm volatile("cp.async.commit_group;" ::: "memory");
        if (it + 1 < NIT3) {
            asm volatile("cp.async.wait_group 1;" ::: "memory");
            __syncthreads();
            int s1 = st_idx + 1; if (s1 >= NSTG3) s1 -= NSTG3;
            uint32_t stn = sb + s1 * STAGE3;
            loadA(stn, 0, a0);
            loadB(stn, 0, b0);
        }
        #pragma unroll
        for (int mi = 0; mi < 4; mi++)
            #pragma unroll
            for (int nj = 0; nj < 8; nj++)
                MMA(acc[mi][nj], a1[mi], &b1[nj >> 1][(nj & 1) * 2]);

        if (++st_idx >= NSTG3) st_idx = 0;
    }

    // epilogue: scale by rowinv, store partial
    #pragma unroll
    for (int mi = 0; mi < 4; mi++) {
        int r0 = rt * 128 + warpM + mi * 16 + (lid >> 2);
        int r1 = r0 + 8;
        float ri0 = (r0 < Nn) ? g_rowinv[r0] : 0.f;
        float ri1 = (r1 < Nn) ? g_rowinv[r1] : 0.f;
        #pragma unroll
        for (int nj = 0; nj < 8; nj++) {
            int n = ct * 128 + warpN + nj * 8 + (lid & 3) * 2;
            if (r0 < Nn) {
                float2 v = make_float2(acc[mi][nj][0] * ri0, acc[mi][nj][1] * ri0);
                *(float2*)&Aggp[(size_t)r0 * NT + n] = v;
            }
            if (r1 < Nn) {
                float2 v = make_float2(acc[mi][nj][2] * ri1, acc[mi][nj][3] * ri1);
                *(float2*)&Aggp[(size_t)r1 * NT + n] = v;
            }
        }
    }
}

// ---------------------------------------------------------------------------
// Kernel 3: epilogue. S = T0 + Agg0 + Agg1; E-weighted combine + biases,
// gates (R, C only), final linear.
// ---------------------------------------------------------------------------
__global__ void __launch_bounds__(128) epilogue_kernel(
    const float* __restrict__ E,
    const float* __restrict__ bgp, const float* __restrict__ bup,
    const float* __restrict__ lw, const float* __restrict__ lb,
    float* __restrict__ out)
{
    __shared__ float sBr[8][2];   // R bias = E . bg[:, 2:4]
    __shared__ float sBc[8][2];   // C bias = E . bu[:, 0:2]
    int n0 = blockIdx.x * 8;
    int tid = threadIdx.x;
    if (tid < 16) {
        int ln = tid >> 1, o = tid & 1; int n = n0 + ln; float v = 0.f;
        if (n < Nn) { for (int d = 0; d < 4; d++) v += E[n * 4 + d] * bgp[d * 4 + 2 + o]; }
        sBr[ln][o] = v;
    } else if (tid < 32) {
        int t = tid - 16, ln = t >> 1, o = t & 1; int n = n0 + ln; float v = 0.f;
        if (n < Nn) { for (int d = 0; d < 4; d++) v += E[n * 4 + d] * bup[d * 2 + o]; }
        sBc[ln][o] = v;
    }
    __syncthreads();

    int ln = tid >> 4, b = tid & 15;
    int n = n0 + ln;
    if (n >= Nn) return;
    float e0 = E[n * 4 + 0], e1 = E[n * 4 + 1], e2 = E[n * 4 + 2], e3 = E[n * 4 + 3];
    size_t base = (size_t)n * NT + b * 16;
    const float4* t0 = (const float4*)(g_T0 + base);
    const float4* g0 = (const float4*)(g_Agg0 + base);
    const float4* g1 = (const float4*)(g_Agg1 + base);
    float S[16];
    #pragma unroll
    for (int q = 0; q < 4; q++) {
        float4 a = t0[q], bq = g0[q], c = g1[q];
        S[q * 4 + 0] = a.x + bq.x + c.x;
        S[q * 4 + 1] = a.y + bq.y + c.y;
        S[q * 4 + 2] = a.z + bq.z + c.z;
        S[q * 4 + 3] = a.w + bq.w + c.w;
    }
    float gr[2], uc[2];
    #pragma unroll
    for (int o = 0; o < 2; o++) {
        gr[o] = sBr[ln][o] + e0 * S[o]     + e1 * S[4 + o]
                           + e2 * S[8 + o] + e3 * S[12 + o];
        uc[o] = sBc[ln][o] + e0 * S[2 + o]  + e1 * S[6 + o]
                           + e2 * S[10 + o] + e3 * S[14 + o];
    }
    float R0 = 1.f / (1.f + __expf(-gr[0]));
    float R1 = 1.f / (1.f + __expf(-gr[1]));
    float C0 = tanhf(uc[0]);
    float C1 = tanhf(uc[1]);
    float h0 = (1.f - R0) * C0;
    float h1 = (1.f - R1) * C1;
    float y = fmaxf(h0, 0.f) * lw[0] + fmaxf(h1, 0.f) * lw[1] + lb[0];
    out[(size_t)b * Nn + n] = y;
}

// ---------------------------------------------------------------------------
extern "C" void kernel_launch(void* const* d_in, const int* in_sizes, int n_in,
                              void* d_out, int out_size) {
    const float* x  = (const float*)d_in[0];
    const float* e  = (const float*)d_in[1];
    const float* wg = (const float*)d_in[2];
    const float* bg = (const float*)d_in[3];
    const float* wu = (const float*)d_in[4];
    const float* bu = (const float*)d_in[5];
    const float* lw = (const float*)d_in[6];
    const float* lb = (const float*)d_in[7];
    float* out = (float*)d_out;

    cudaFuncSetAttribute(gemm_mma_kernel,
                         cudaFuncAttributeMaxDynamicSharedMemorySize, SMEM_TOTAL3);

    normmax_kernel<<<(Nn + 255) / 256, 256>>>(e);
    fused_prep_kernel<<<MP / 8 + KK / 16, 256>>>(e, x, wg, wu);
    gemm_mma_kernel<<<dim3(MT, CT, 2), 128, SMEM_TOTAL3>>>();
    epilogue_kernel<<<(Nn + 7) / 8, 128>>>(e, bg, bu, lw, lb, out);
}

// round 16
// speedup vs baseline: 1.2287x; 1.1067x over previous
#include <cuda_runtime.h>
#include <cuda_fp16.h>
#include <cstdint>

// ---------------------------------------------------------------------------
// Problem constants
// ---------------------------------------------------------------------------
#define Nn 5570          // nodes
#define NT 256           // live aggregation columns = B(16) * D(4) * 4 (Z dropped)
#define MP 5632          // M padded: 44 tiles of 128
#define KK 5632          // K padded
#define MT 44            // row tiles
#define CT 2             // col tiles (2 x 128 = 256)
#define KSLICES 3        // K split: iters 30/30/28 of BK=64 (1920/1920/1792)

// ---------------------------------------------------------------------------
// Device scratch
// Column layout (per m/n row): j = b*16 + d*4 + o,
//   o in {0,1} -> R gate outputs (original gate cols 2,3)
//   o in {2,3} -> C update outputs (original update cols 0,1)
// ---------------------------------------------------------------------------
__device__ __align__(128) uint32_t g_A[(size_t)MP * KK / 2];
__device__ __align__(128) uint32_t g_B[(size_t)KK * NT / 2];
__device__ float g_T0[(size_t)KK * NT];     // k=0 (identity) per-node partials
__device__ float g_rowinv[MP];
__device__ float g_Agg[(size_t)KSLICES * MP * NT];  // K-slice partials
__device__ unsigned int g_gmax2_bits = 0u;  // max_m |e_m|^2 bits (atomicMax is
                                            // idempotent across graph replays)

// ---------------------------------------------------------------------------
// Helpers
// ---------------------------------------------------------------------------
__device__ __forceinline__ uint32_t smem_u32(const void* p) {
    uint32_t a;
    asm("{ .reg .u64 t; cvta.to.shared.u64 t, %1; cvt.u32.u64 %0, t; }" : "=r"(a) : "l"(p));
    return a;
}

// 2^t on the FMA pipe for t <= 0, t >= -127. ~4e-5 relative error.
__device__ __forceinline__ float fexp2n(float t) {
    float km = t + 12582912.0f;                 // round-to-nearest magic
    int   ki = __float_as_int(km);
    float f  = t - (km - 12582912.0f);          // f in [-0.5, 0.5]
    float p  = 9.6180691e-3f;
    p = fmaf(p, f, 5.5504109e-2f);
    p = fmaf(p, f, 2.4022651e-1f);
    p = fmaf(p, f, 6.9314718e-1f);
    p = fmaf(p, f, 1.0f);
    float sc = __int_as_float((ki - (0x4B400000 - 127)) << 23);  // 2^round(t)
    return p * sc;
}

#define LOG2E 1.4426950408889634f

// ---------------------------------------------------------------------------
// Micro-kernel: global max of |e_m|^2
// ---------------------------------------------------------------------------
__global__ void __launch_bounds__(256) normmax_kernel(const float* __restrict__ E) {
    int m = blockIdx.x * 256 + threadIdx.x;
    float v = 0.f;
    if (m < Nn) {
        float4 em = ((const float4*)E)[m];
        v = fmaf(em.x, em.x, fmaf(em.y, em.y, fmaf(em.z, em.z, em.w * em.w)));
    }
    #pragma unroll
    for (int o = 16; o > 0; o >>= 1) v = fmaxf(v, __shfl_xor_sync(0xffffffffu, v, o));
    if ((threadIdx.x & 31) == 0)
        atomicMax(&g_gmax2_bits, __float_as_uint(v));  // positive floats: uint order
}

// ---------------------------------------------------------------------------
// Kernel 1 (fused): blocks [0, 704): bounded-softmax P -> fp16 (single pass,
//                   log2-domain exp).
//                   blocks [704, 1056): T^T (k=1 -> fp16 B) and T0 (k=0 -> fp32),
//                   x staged through SMEM for coalescing.
// ---------------------------------------------------------------------------
__global__ void __launch_bounds__(256) fused_prep_kernel(
    const float* __restrict__ E, const float* __restrict__ x,
    const float* __restrict__ wg, const float* __restrict__ wu)
{
    int tid = threadIdx.x;
    if (blockIdx.x < MP / 8) {
        // ---------------- exp part: one warp per row, single pass -------------
        int row  = blockIdx.x * 8 + (tid >> 5);
        int lane = tid & 31;
        const float4* E4 = (const float4*)E;
        bool valid = (row < Nn);
        float4 en = make_float4(0.f, 0.f, 0.f, 0.f);
        if (valid) en = E4[row];
        float en2 = fmaf(en.x, en.x, fmaf(en.y, en.y, fmaf(en.z, en.z, en.w * en.w)));
        float gmax2 = __uint_as_float(g_gmax2_bits);
        // Cauchy-Schwarz bound in log2 units: M2 >= log2e * max_m en.em
        float M2 = sqrtf(en2 * gmax2) * LOG2E;
        // pre-scale en so dot products land directly in log2 domain
        en.x *= LOG2E; en.y *= LOG2E; en.z *= LOG2E; en.w *= LOG2E;

        size_t rbase = (size_t)row * (KK / 2);
        float sum = 0.f;
        for (int kc = 0; kc < KK / 64; kc++) {
            int k0 = kc * 64 + lane * 2;
            float p0 = 0.f, p1 = 0.f;
            if (valid && k0 < Nn) {
                float4 e0 = __ldg(&E4[k0]);
                float4 e1 = __ldg(&E4[k0 + 1]);
                float t0 = fmaf(en.x, e0.x, fmaf(en.y, e0.y, fmaf(en.z, e0.z, en.w * e0.w)));
                float t1 = fmaf(en.x, e1.x, fmaf(en.y, e1.y, fmaf(en.z, e1.z, en.w * e1.w)));
                p0 = fexp2n(fmaxf(t0, 0.f) - M2);
                p1 = fexp2n(fmaxf(t1, 0.f) - M2);
            }
            sum += p0 + p1;
            __half2 h = __floats2half2_rn(p0, p1);
            g_A[rbase + kc * 32 + lane] = *reinterpret_cast<uint32_t*>(&h);
        }
        #pragma unroll
        for (int o = 16; o > 0; o >>= 1) sum += __shfl_xor_sync(0xffffffffu, sum, o);
        if (valid && lane == 0) g_rowinv[row] = 1.f / sum;
    } else {
        // -------- T parts: 16 m-rows x 16 batches per block, live cols only ----
        // j = d*4 + o: o<2 -> gate col (o+2) [R], o>=2 -> update col (o-2) [C]
        __shared__ float sW1[35][16];   // k=1 support weights
        __shared__ float sW0[35][16];   // k=0 (identity) weights
        __shared__ float sx[16][565];   // staged x[b][mlocal*35 + i], pitch 565
        for (int idx = tid; idx < 35 * 16; idx += 256) {
            int i = idx / 16, j = idx % 16, d = j / 4, o = j % 4;
            sW1[i][j] = (o < 2) ? wg[((d * 2 + 1) * 37 + i) * 4 + (o + 2)]
                                : wu[((d * 2 + 1) * 37 + i) * 2 + (o - 2)];
            sW0[i][j] = (o < 2) ? wg[((d * 2) * 37 + i) * 4 + (o + 2)]
                                : wu[((d * 2) * 37 + i) * 2 + (o - 2)];
        }
        int bb = blockIdx.x - MP / 8;
        int m0 = bb * 16;
        // stage x: 16 batches x 560 contiguous floats each (coalesced)
        if (m0 + 16 <= Nn) {
            for (int j = tid; j < 16 * 560; j += 256) {
                int b = j / 560, r = j - b * 560;
                sx[b][r] = x[((size_t)b * Nn + m0) * 35 + r];
            }
        } else {
            for (int j = tid; j < 16 * 560; j += 256) {
                int b = j / 560, r = j - b * 560;
                int m = m0 + r / 35;
                sx[b][r] = (m < Nn) ? x[((size_t)b * Nn + m0) * 35 + r] : 0.f;
            }
        }
        __syncthreads();

        int ml = tid >> 4;              // local m (0..15)
        int m  = m0 + ml;
        int b  = tid & 15;
        float ak[16], az[16];           // k=1 and k=0 accumulators
        #pragma unroll
        for (int j = 0; j < 16; j++) { ak[j] = 0.f; az[j] = 0.f; }
        if (m < Nn) {
            const float* xs = &sx[b][ml * 35];
            for (int i = 0; i < 35; i++) {
                float xv = xs[i];
                #pragma unroll
                for (int j = 0; j < 16; j++) {
                    ak[j] = fmaf(xv, sW1[i][j], ak[j]);
                    az[j] = fmaf(xv, sW0[i][j], az[j]);
                }
            }
        }
        size_t baseB = (size_t)m * (NT / 2) + b * 8;
        #pragma unroll
        for (int j = 0; j < 8; j++) {
            __half2 h = __floats2half2_rn(ak[2 * j], ak[2 * j + 1]);
            g_B[baseB + j] = *reinterpret_cast<uint32_t*>(&h);
        }
        float* t0p = g_T0 + (size_t)m * NT + b * 16;
        #pragma unroll
        for (int j = 0; j < 4; j++) {
            float4 v = make_float4(az[4 * j], az[4 * j + 1], az[4 * j + 2], az[4 * j + 3]);
            *(float4*)&t0p[4 * j] = v;
        }
    }
}

// ---------------------------------------------------------------------------
// Kernel 2: GEMM partials Agg[z] = rowinv * (P[:, slice z] @ T[slice z]).
// Grid (44, 2, 3); slices 1920/1920/1792 (30/30/28 iters of BK=64).
// CTA 128x128, 4 warps (64x64 tiles), 3-stage cp.async pipeline + register
// double-buffering at k16 granularity. 2 CTAs/SM. Pitches 144/272.
// ---------------------------------------------------------------------------
#define APITCH3 144
#define BPITCH3 272
#define ASZ3 (128 * APITCH3)          // 18432
#define BSZ3 (64 * BPITCH3)           // 17408
#define BOFF3 ASZ3
#define STAGE3 (ASZ3 + BSZ3)          // 35840
#define NSTG3 3
#define SMEM_TOTAL3 (NSTG3 * STAGE3)  // 107520 (x2 CTAs = 215KB <= 228KB)

__device__ __forceinline__ void cpasync16(uint32_t dst, const void* src) {
    asm volatile("cp.async.cg.shared.global [%0], [%1], 16;" :: "r"(dst), "l"(src));
}
__device__ __forceinline__ void ldsm4(uint32_t* r, uint32_t addr) {
    asm volatile("ldmatrix.sync.aligned.m8n8.x4.shared.b16 {%0,%1,%2,%3}, [%4];"
        : "=r"(r[0]), "=r"(r[1]), "=r"(r[2]), "=r"(r[3]) : "r"(addr));
}
__device__ __forceinline__ void ldsm4t(uint32_t* r, uint32_t addr) {
    asm volatile("ldmatrix.sync.aligned.m8n8.x4.trans.shared.b16 {%0,%1,%2,%3}, [%4];"
        : "=r"(r[0]), "=r"(r[1]), "=r"(r[2]), "=r"(r[3]) : "r"(addr));
}
#define MMA(acc, a, b) \
    asm volatile("mma.sync.aligned.m16n8k16.row.col.f32.f16.f16.f32 " \
        "{%0,%1,%2,%3}, {%4,%5,%6,%7}, {%8,%9}, {%0,%1,%2,%3};" \
        : "+f"((acc)[0]), "+f"((acc)[1]), "+f"((acc)[2]), "+f"((acc)[3]) \
        : "r"((a)[0]), "r"((a)[1]), "r"((a)[2]), "r"((a)[3]), \
          "r"((b)[0]), "r"((b)[1]))

__global__ void __launch_bounds__(128, 2) gemm_mma_kernel() {
    extern __shared__ __align__(128) char smem[];
    uint32_t sb = smem_u32(smem);
    int tid = threadIdx.x, wid = tid >> 5, lid = tid & 31;
    int rt = blockIdx.x, ct = blockIdx.y, ks = blockIdx.z;
    int kbase = ks * 1920;
    int nit = (ks == 2) ? 28 : 30;
    int warpM = (wid >> 1) * 64;        // 0 or 64
    int warpN = (wid & 1) * 64;         // 0 or 64

    const char* Ab = (const char*)g_A + ((size_t)rt * 128 * KK + (size_t)kbase) * 2;
    const char* Bb = (const char*)g_B + ((size_t)kbase * NT + (size_t)ct * 128) * 2;
    float* Aggp = g_Agg + (size_t)ks * MP * NT;

    float acc[4][8][4];
    #pragma unroll
    for (int mi = 0; mi < 4; mi++)
        #pragma unroll
        for (int nj = 0; nj < 8; nj++)
            #pragma unroll
            for (int q = 0; q < 4; q++) acc[mi][nj][q] = 0.f;

    // ldmatrix per-lane address components
    int aRow = lid & 15, aK = lid >> 4;                        // A
    int bK = (lid & 7) + ((lid >> 3) & 1) * 8;                 // B (trans)
    int bN = ((lid >> 4) & 1) * 8;

    auto issue = [&](int s, int k0) {
        uint32_t d = sb + s * STAGE3;
        // A: 128 rows x 64 k = 1024 16B-chunks (8/thread)
        #pragma unroll
        for (int i = 0; i < 8; i++) {
            int ci = tid + i * 128;
            int ar = ci >> 3, ak = ci & 7;
            cpasync16(d + ar * APITCH3 + ak * 16,
                      Ab + ((size_t)ar * KK + k0 + ak * 8) * 2);
        }
        // B: 64 k-rows x 128 cols = 1024 16B-chunks (8/thread)
        #pragma unroll
        for (int i = 0; i < 8; i++) {
            int ci = tid + i * 128;
            int bk = ci >> 4, bc = ci & 15;
            cpasync16(d + BOFF3 + bk * BPITCH3 + bc * 16,
                      Bb + ((size_t)(k0 + bk) * NT + bc * 8) * 2);
        }
    };
    auto loadA = [&](uint32_t st, int k16, uint32_t (*a)[4]) {
        #pragma unroll
        for (int mi = 0; mi < 4; mi++)
            ldsm4(a[mi], st + (warpM + mi * 16 + aRow) * APITCH3 + k16 * 32 + aK * 16);
    };
    auto loadB = [&](uint32_t st, int k16, uint32_t (*b)[4]) {
        #pragma unroll
        for (int nb = 0; nb < 4; nb++)
            ldsm4t(b[nb], st + BOFF3 + (k16 * 16 + bK) * BPITCH3 + (warpN + nb * 16 + bN) * 2);
    };

    uint32_t a0[4][4], b0[4][4], a1[4][4], b1[4][4];

    // prologue: fill 2 stages, then preload (it=0, k16=0) fragments
    issue(0, 0);
    asm volatile("cp.async.commit_group;" ::: "memory");
    issue(1, 64);
    asm volatile("cp.async.commit_group;" ::: "memory");
    asm volatile("cp.async.wait_group 1;" ::: "memory");
    __syncthreads();
    loadA(sb, 0, a0);
    loadB(sb, 0, b0);

    int st_idx = 0;
    for (int it = 0; it < nit; it++) {
        uint32_t st = sb + st_idx * STAGE3;

        // k16 = 0: prefetch k16=1, MMA buf0
        loadA(st, 1, a1);
        loadB(st, 1, b1);
        #pragma unroll
        for (int mi = 0; mi < 4; mi++)
            #pragma unroll
            for (int nj = 0; nj < 8; nj++)
                MMA(acc[mi][nj], a0[mi], &b0[nj >> 1][(nj & 1) * 2]);

        // k16 = 1: prefetch k16=2, MMA buf1
        loadA(st, 2, a0);
        loadB(st, 2, b0);
        #pragma unroll
        for (int mi = 0; mi < 4; mi++)
            #pragma unroll
            for (int nj = 0; nj < 8; nj++)
                MMA(acc[mi][nj], a1[mi], &b1[nj >> 1][(nj & 1) * 2]);

        // k16 = 2: prefetch k16=3, MMA buf0
        loadA(st, 3, a1);
        loadB(st, 3, b1);
        #pragma unroll
        for (int mi = 0; mi < 4; mi++)
            #pragma unroll
            for (int nj = 0; nj < 8; nj++)
                MMA(acc[mi][nj], a0[mi], &b0[nj >> 1][(nj & 1) * 2]);

        // refill pipeline + advance; then MMA buf1 (k16 = 3)
        int nxt = it + 2;
        int nstage = st_idx + 2; if (nstage >= NSTG3) nstage -= NSTG3;
        if (nxt < nit) issue(nstage, nxt * 64);
        asm volatile("cp.async.commit_group;" ::: "memory");
        if (it + 1 < nit) {
            asm volatile("cp.async.wait_group 1;" ::: "memory");
            __syncthreads();
            int s1 = st_idx + 1; if (s1 >= NSTG3) s1 -= NSTG3;
            uint32_t stn = sb + s1 * STAGE3;
            loadA(stn, 0, a0);
            loadB(stn, 0, b0);
        }
        #pragma unroll
        for (int mi = 0; mi < 4; mi++)
            #pragma unroll
            for (int nj = 0; nj < 8; nj++)
                MMA(acc[mi][nj], a1[mi], &b1[nj >> 1][(nj & 1) * 2]);

        if (++st_idx >= NSTG3) st_idx = 0;
    }

    // epilogue: scale by rowinv, store partial
    #pragma unroll
    for (int mi = 0; mi < 4; mi++) {
        int r0 = rt * 128 + warpM + mi * 16 + (lid >> 2);
        int r1 = r0 + 8;
        float ri0 = (r0 < Nn) ? g_rowinv[r0] : 0.f;
        float ri1 = (r1 < Nn) ? g_rowinv[r1] : 0.f;
        #pragma unroll
        for (int nj = 0; nj < 8; nj++) {
            int n = ct * 128 + warpN + nj * 8 + (lid & 3) * 2;
            if (r0 < Nn) {
                float2 v = make_float2(acc[mi][nj][0] * ri0, acc[mi][nj][1] * ri0);
                *(float2*)&Aggp[(size_t)r0 * NT + n] = v;
            }
            if (r1 < Nn) {
                float2 v = make_float2(acc[mi][nj][2] * ri1, acc[mi][nj][3] * ri1);
                *(float2*)&Aggp[(size_t)r1 * NT + n] = v;
            }
        }
    }
}

// ---------------------------------------------------------------------------
// Kernel 3: epilogue. S = T0 + Agg[0] + Agg[1] + Agg[2]; E-weighted combine
// + biases, gates (R, C only), final linear.
// ---------------------------------------------------------------------------
__global__ void __launch_bounds__(128) epilogue_kernel(
    const float* __restrict__ E,
    const float* __restrict__ bgp, const float* __restrict__ bup,
    const float* __restrict__ lw, const float* __restrict__ lb,
    float* __restrict__ out)
{
    __shared__ float sBr[8][2];   // R bias = E . bg[:, 2:4]
    __shared__ float sBc[8][2];   // C bias = E . bu[:, 0:2]
    int n0 = blockIdx.x * 8;
    int tid = threadIdx.x;
    if (tid < 16) {
        int ln = tid >> 1, o = tid & 1; int n = n0 + ln; float v = 0.f;
        if (n < Nn) { for (int d = 0; d < 4; d++) v += E[n * 4 + d] * bgp[d * 4 + 2 + o]; }
        sBr[ln][o] = v;
    } else if (tid < 32) {
        int t = tid - 16, ln = t >> 1, o = t & 1; int n = n0 + ln; float v = 0.f;
        if (n < Nn) { for (int d = 0; d < 4; d++) v += E[n * 4 + d] * bup[d * 2 + o]; }
        sBc[ln][o] = v;
    }
    __syncthreads();

    int ln = tid >> 4, b = tid & 15;
    int n = n0 + ln;
    if (n >= Nn) return;
    float e0 = E[n * 4 + 0], e1 = E[n * 4 + 1], e2 = E[n * 4 + 2], e3 = E[n * 4 + 3];
    size_t base = (size_t)n * NT + b * 16;
    const float4* t0 = (const float4*)(g_T0 + base);
    const float4* g0 = (const float4*)(g_Agg + base);
    const float4* g1 = (const float4*)(g_Agg + (size_t)MP * NT + base);
    const float4* g2 = (const float4*)(g_Agg + 2 * (size_t)MP * NT + base);
    float S[16];
    #pragma unroll
    for (int q = 0; q < 4; q++) {
        float4 a = t0[q], bq = g0[q], c = g1[q], d = g2[q];
        S[q * 4 + 0] = a.x + bq.x + c.x + d.x;
        S[q * 4 + 1] = a.y + bq.y + c.y + d.y;
        S[q * 4 + 2] = a.z + bq.z + c.z + d.z;
        S[q * 4 + 3] = a.w + bq.w + c.w + d.w;
    }
    float gr[2], uc[2];
    #pragma unroll
    for (int o = 0; o < 2; o++) {
        gr[o] = sBr[ln][o] + e0 * S[o]     + e1 * S[4 + o]
                           + e2 * S[8 + o] + e3 * S[12 + o];
        uc[o] = sBc[ln][o] + e0 * S[2 + o]  + e1 * S[6 + o]
                           + e2 * S[10 + o] + e3 * S[14 + o];
    }
    float R0 = 1.f / (1.f + __expf(-gr[0]));
    float R1 = 1.f / (1.f + __expf(-gr[1]));
    float C0 = tanhf(uc[0]);
    float C1 = tanhf(uc[1]);
    float h0 = (1.f - R0) * C0;
    float h1 = (1.f - R1) * C1;
    float y = fmaxf(h0, 0.f) * lw[0] + fmaxf(h1, 0.f) * lw[1] + lb[0];
    out[(size_t)b * Nn + n] = y;
}

// ---------------------------------------------------------------------------
extern "C" void kernel_launch(void* const* d_in, const int* in_sizes, int n_in,
                              void* d_out, int out_size) {
    const float* x  = (const float*)d_in[0];
    const float* e  = (const float*)d_in[1];
    const float* wg = (const float*)d_in[2];
    const float* bg = (const float*)d_in[3];
    const float* wu = (const float*)d_in[4];
    const float* bu = (const float*)d_in[5];
    const float* lw = (const float*)d_in[6];
    const float* lb = (const float*)d_in[7];
    float* out = (float*)d_out;

    cudaFuncSetAttribute(gemm_mma_kernel,
                         cudaFuncAttributeMaxDynamicSharedMemorySize, SMEM_TOTAL3);

    normmax_kernel<<<(Nn + 255) / 256, 256>>>(e);
    fused_prep_kernel<<<MP / 8 + KK / 16, 256>>>(e, x, wg, wu);
    gemm_mma_kernel<<<dim3(MT, CT, KSLICES), 128, SMEM_TOTAL3>>>();
    epilogue_kernel<<<(Nn + 7) / 8, 128>>>(e, bg, bu, lw, lb, out);
}